// round 11
// baseline (speedup 1.0000x reference)
#include <cuda_runtime.h>
#include <cuda_bf16.h>

#define NN    30000
#define EE    600000
#define IN_C  256
#define HID_C 128
#define OUT_C 64

typedef unsigned int       u32;
typedef unsigned long long u64;
typedef unsigned short     u16;

// ---------------- device scratch ----------------
__device__ int   g_src[EE];
__device__ int   g_dst[EE];
__device__ int   g_deg[NN];
__device__ float g_dinv[NN];
__device__ int   g_ptr[NN + 1];
__device__ int   g_cur[NN];
__device__ int2  g_csr[EE];
__device__ float g_h1[NN * HID_C];          // X@W1 (fp32, gathered by agg1)
__device__ u32   g_a1h[NN * HID_C / 2];     // relu(agg1) bf16-hi pairs
__device__ u32   g_a1l[NN * HID_C / 2];     // relu(agg1) bf16-lo pairs
__device__ float g_h2[NN * OUT_C];          // agg1@W2
__device__ u32   g_w1th[HID_C * IN_C / 2];  // W1^T bf16 hi  [128][256]
__device__ u32   g_w1tl[HID_C * IN_C / 2];
__device__ u32   g_w2th[OUT_C * HID_C / 2]; // W2^T bf16 hi  [64][128]
__device__ u32   g_w2tl[OUT_C * HID_C / 2];

// ---------------- helpers ----------------
__device__ __forceinline__ u32 pack_bf2(__nv_bfloat16 a, __nv_bfloat16 b) {
    return (u32)__bfloat16_as_ushort(a) | ((u32)__bfloat16_as_ushort(b) << 16);
}
__device__ __forceinline__ void split_bf(float v, __nv_bfloat16& h, __nv_bfloat16& l) {
    h = __float2bfloat16(v);
    l = __float2bfloat16(v - __bfloat162float(h));
}
__device__ __forceinline__ void ldsm4(u32* r, const void* p) {
    u32 addr = (u32)__cvta_generic_to_shared(p);
    asm volatile("ldmatrix.sync.aligned.m8n8.x4.shared.b16 {%0,%1,%2,%3}, [%4];"
                 : "=r"(r[0]), "=r"(r[1]), "=r"(r[2]), "=r"(r[3]) : "r"(addr));
}
__device__ __forceinline__ void mma_bf16(float* d, const u32* a, u32 b0, u32 b1) {
    asm volatile("mma.sync.aligned.m16n8k16.row.col.f32.bf16.bf16.f32 "
                 "{%0,%1,%2,%3}, {%4,%5,%6,%7}, {%8,%9}, {%0,%1,%2,%3};"
                 : "+f"(d[0]), "+f"(d[1]), "+f"(d[2]), "+f"(d[3])
                 : "r"(a[0]), "r"(a[1]), "r"(a[2]), "r"(a[3]), "r"(b0), "r"(b1));
}

// ---------------- prep kernels ----------------
__global__ void zero_deg_kernel() {
    int i = blockIdx.x * blockDim.x + threadIdx.x;
    if (i < NN) g_deg[i] = 0;
}

__global__ void prep_edges_kernel(const unsigned* __restrict__ raw) {
    __shared__ int s_is64;
    if (threadIdx.x == 0) {
        int is64 = 1;
        for (int i = 1; i < 64; i += 2)
            if (raw[i] != 0u) { is64 = 0; break; }
        s_is64 = is64;
    }
    __syncthreads();
    int e = blockIdx.x * blockDim.x + threadIdx.x;
    if (e >= EE) return;
    int s, d;
    if (s_is64) {
        const long long* p = (const long long*)raw;
        s = (int)p[e]; d = (int)p[EE + e];
    } else {
        const int* p = (const int*)raw;
        s = p[e]; d = p[EE + e];
    }
    g_src[e] = s;
    g_dst[e] = d;
    atomicAdd(&g_deg[d], 1);
}

// W1^T and W2^T bf16 hi/lo split (transpose to K-major rows).
__global__ void wprep_kernel(const float* __restrict__ W1, const float* __restrict__ W2) {
    int i = blockIdx.x * blockDim.x + threadIdx.x;
    u16* w1th = (u16*)g_w1th; u16* w1tl = (u16*)g_w1tl;
    u16* w2th = (u16*)g_w2th; u16* w2tl = (u16*)g_w2tl;
    if (i < IN_C * HID_C) {
        int k = i / HID_C, n = i % HID_C;
        __nv_bfloat16 h, l; split_bf(W1[i], h, l);
        w1th[n * IN_C + k] = __bfloat16_as_ushort(h);
        w1tl[n * IN_C + k] = __bfloat16_as_ushort(l);
    } else {
        int j = i - IN_C * HID_C;
        if (j < HID_C * OUT_C) {
            int k = j / OUT_C, n = j % OUT_C;
            __nv_bfloat16 h, l; split_bf(W2[j], h, l);
            w2th[n * HID_C + k] = __bfloat16_as_ushort(h);
            w2tl[n * HID_C + k] = __bfloat16_as_ushort(l);
        }
    }
}

// Fused scan + dinv: single block, 1024 threads, 30 elems/thread, warp-shfl scan.
__global__ void __launch_bounds__(1024) scan_dinv_kernel() {
    constexpr int PER = 30;   // 1024*30 = 30720 >= NN
    int tid = threadIdx.x;
    int base = tid * PER;
    int d[PER];
    int tot = 0;
#pragma unroll
    for (int i = 0; i < PER; i++) {
        int idx = base + i;
        d[i] = (idx < NN) ? g_deg[idx] : 0;
        tot += d[i];
    }
    int lane = tid & 31, warp = tid >> 5;
    int run = tot;
#pragma unroll
    for (int off = 1; off < 32; off <<= 1) {
        int n = __shfl_up_sync(0xffffffffu, run, off);
        if (lane >= off) run += n;
    }
    __shared__ int wsum[32];
    if (lane == 31) wsum[warp] = run;
    __syncthreads();
    if (warp == 0) {
        int v = wsum[lane];
        int r = v;
#pragma unroll
        for (int off = 1; off < 32; off <<= 1) {
            int n = __shfl_up_sync(0xffffffffu, r, off);
            if (lane >= off) r += n;
        }
        wsum[lane] = r - v;    // exclusive warp prefix
    }
    __syncthreads();
    int p = wsum[warp] + run - tot;  // global exclusive prefix
#pragma unroll
    for (int i = 0; i < PER; i++) {
        int idx = base + i;
        if (idx < NN) {
            g_ptr[idx] = p;
            g_cur[idx] = p;
            g_dinv[idx] = rsqrtf((float)(d[i] + 1));
        }
        p += d[i];
    }
    if (tid == 1023) g_ptr[NN] = p;
}

__global__ void fill_csr_kernel() {
    int e = blockIdx.x * blockDim.x + threadIdx.x;
    if (e >= EE) return;
    int s = g_src[e];
    int dd = g_dst[e];
    int slot = atomicAdd(&g_cur[dd], 1);
    g_csr[slot] = make_int2(s, __float_as_int(g_dinv[s] * g_dinv[dd]));
}

// ---------------- bf16x3 mma.sync GEMM:  C[M,BN] = A[M,KTOT] @ (Bt)^T ----------------
// Bt is [BN][KTOT] bf16 hi/lo (K-major = col-major B for mma row.col).
// A is fp32 (split in-kernel) or pre-split bf16 pairs.
// Block 128xBN, 8 warps in 4(m) x 2(n); warp tile 32 x (BN/2); BK=32.
template<int BN, int KTOT, bool AF32>
__global__ void __launch_bounds__(256, 1)
mma_gemm(const float* __restrict__ Af,
         const u32* __restrict__ Ah32, const u32* __restrict__ Al32,
         const u32* __restrict__ Bh, const u32* __restrict__ Bl,
         float* __restrict__ C)
{
    constexpr int BK   = 32;
    constexpr int LDS  = 40;            // padded row stride in bf16 (80B, ldmatrix conflict-free)
    constexpr int NCH  = KTOT / BK;
    constexpr int WN   = BN / 2;        // 64 (L1) or 32 (L2)
    constexpr int NI16 = WN / 16;       // 4 or 2

    __shared__ __align__(16) u16 sAh[128][LDS];
    __shared__ __align__(16) u16 sAl[128][LDS];
    __shared__ __align__(16) u16 sBh[BN][LDS];
    __shared__ __align__(16) u16 sBl[BN][LDS];

    const int tid  = threadIdx.x;
    const int warp = tid >> 5, lane = tid & 31;
    const int wm = warp & 3;            // m warp: 32*wm
    const int wn = warp >> 2;           // n warp: WN*wn
    const int m0 = blockIdx.x * 128;
    const int sub = lane >> 3, r8 = lane & 7;

    float acc[2][2 * NI16][4];
#pragma unroll
    for (int i = 0; i < 2; i++)
#pragma unroll
        for (int j = 0; j < 2 * NI16; j++)
#pragma unroll
            for (int q = 0; q < 4; q++) acc[i][j][q] = 0.0f;

    for (int c = 0; c < NCH; c++) {
        // ---- load A chunk (128 x 32) ----
        if (AF32) {
            for (int idx = tid; idx < 1024; idx += 256) {     // 128 rows x 8 float4
                int row = idx >> 3, f4 = idx & 7;
                int gm = m0 + row;
                float4 v = make_float4(0.f, 0.f, 0.f, 0.f);
                if (gm < NN) v = *(const float4*)(Af + (size_t)gm * KTOT + c * BK + f4 * 4);
                __nv_bfloat16 hx, lx, hy, ly, hz, lz, hw, lw;
                split_bf(v.x, hx, lx); split_bf(v.y, hy, ly);
                split_bf(v.z, hz, lz); split_bf(v.w, hw, lw);
                *(uint2*)&sAh[row][f4 * 4] = make_uint2(pack_bf2(hx, hy), pack_bf2(hz, hw));
                *(uint2*)&sAl[row][f4 * 4] = make_uint2(pack_bf2(lx, ly), pack_bf2(lz, lw));
            }
        } else {
            for (int idx = tid; idx < 2048; idx += 256) {     // 128 rows x 16 u32
                int row = idx >> 4, uu = idx & 15;
                int gm = m0 + row;
                u32 hv = 0, lv = 0;
                if (gm < NN) {
                    size_t g = (size_t)gm * (KTOT / 2) + c * (BK / 2) + uu;
                    hv = Ah32[g]; lv = Al32[g];
                }
                *(u32*)&sAh[row][uu * 2] = hv;
                *(u32*)&sAl[row][uu * 2] = lv;
            }
        }
        // ---- load B chunk (BN x 32) ----
        for (int idx = tid; idx < BN * 16; idx += 256) {
            int row = idx >> 4, uu = idx & 15;
            size_t g = (size_t)row * (KTOT / 2) + c * (BK / 2) + uu;
            *(u32*)&sBh[row][uu * 2] = Bh[g];
            *(u32*)&sBl[row][uu * 2] = Bl[g];
        }
        __syncthreads();

#pragma unroll
        for (int kk = 0; kk < BK; kk += 16) {
            // A fragments (hi+lo) for this warp's 32 rows
            u32 ah[2][4], al[2][4];
#pragma unroll
            for (int mi = 0; mi < 2; mi++) {
                int arow = wm * 32 + mi * 16 + ((sub & 1) << 3) + r8;
                int acol = kk + ((sub >> 1) << 3);
                ldsm4(ah[mi], &sAh[arow][acol]);
                ldsm4(al[mi], &sAl[arow][acol]);
            }
#pragma unroll
            for (int ni = 0; ni < NI16; ni++) {
                int brow = wn * WN + ni * 16 + ((sub >> 1) << 3) + r8;
                int bcol = kk + ((sub & 1) << 3);
                u32 bh[4], bl[4];
                ldsm4(bh, &sBh[brow][bcol]);
                ldsm4(bl, &sBl[brow][bcol]);
#pragma unroll
                for (int mi = 0; mi < 2; mi++) {
                    mma_bf16(acc[mi][ni * 2 + 0], ah[mi], bh[0], bh[1]);
                    mma_bf16(acc[mi][ni * 2 + 1], ah[mi], bh[2], bh[3]);
                    mma_bf16(acc[mi][ni * 2 + 0], ah[mi], bl[0], bl[1]);
                    mma_bf16(acc[mi][ni * 2 + 1], ah[mi], bl[2], bl[3]);
                    mma_bf16(acc[mi][ni * 2 + 0], al[mi], bh[0], bh[1]);
                    mma_bf16(acc[mi][ni * 2 + 1], al[mi], bh[2], bh[3]);
                }
            }
        }
        __syncthreads();
    }

    // ---- epilogue ----
#pragma unroll
    for (int mi = 0; mi < 2; mi++) {
#pragma unroll
        for (int j = 0; j < 2 * NI16; j++) {
            int row = m0 + wm * 32 + mi * 16 + (lane >> 2);
            int col = wn * WN + j * 8 + (lane & 3) * 2;
            float* dst = C + (size_t)row * BN + col;
            if (row < NN) {
                dst[0] = acc[mi][j][0];
                dst[1] = acc[mi][j][1];
            }
            if (row + 8 < NN) {
                dst[8 * BN + 0] = acc[mi][j][2];
                dst[8 * BN + 1] = acc[mi][j][3];
            }
        }
    }
}

// ---------------- CSR pull-aggregation, layer 1 (F=128) ----------------
// out = relu(b1 + h[n]*dinv^2 + sum h[src]*norm), written as bf16 hi/lo pairs.
__global__ void __launch_bounds__(256)
agg1_kernel(const float4* __restrict__ h, const float* __restrict__ bias,
            u32* __restrict__ outh, u32* __restrict__ outl)
{
    int warp = threadIdx.x >> 5;
    int lane = threadIdx.x & 31;
    int node = blockIdx.x * 8 + warp;

    float dv  = g_dinv[node];
    float dv2 = dv * dv;
    float4 b  = ((const float4*)bias)[lane];
    float4 sv = h[(size_t)node * 32 + lane];
    float4 acc = make_float4(b.x + sv.x * dv2, b.y + sv.y * dv2,
                             b.z + sv.z * dv2, b.w + sv.w * dv2);

    int beg = g_ptr[node], end = g_ptr[node + 1];
    for (int k = beg; k < end; k += 32) {
        int idx = k + lane;
        int2 pr = (idx < end) ? g_csr[idx] : make_int2(0, 0);
        int cnt = min(32, end - k);
        for (int i = 0; i < cnt; i++) {
            int   ss = __shfl_sync(0xffffffffu, pr.x, i);
            float nn = __int_as_float(__shfl_sync(0xffffffffu, pr.y, i));
            float4 v = h[(size_t)ss * 32 + lane];
            acc.x += v.x * nn; acc.y += v.y * nn;
            acc.z += v.z * nn; acc.w += v.w * nn;
        }
    }
    float4 v = make_float4(fmaxf(acc.x, 0.f), fmaxf(acc.y, 0.f),
                           fmaxf(acc.z, 0.f), fmaxf(acc.w, 0.f));
    __nv_bfloat16 hx, lx, hy, ly, hz, lz, hw, lw;
    split_bf(v.x, hx, lx); split_bf(v.y, hy, ly);
    split_bf(v.z, hz, lz); split_bf(v.w, hw, lw);
    size_t o = (size_t)node * 64 + lane * 2;
    *(uint2*)(outh + o) = make_uint2(pack_bf2(hx, hy), pack_bf2(hz, hw));
    *(uint2*)(outl + o) = make_uint2(pack_bf2(lx, ly), pack_bf2(lz, lw));
}

// ---------------- CSR pull-aggregation, layer 2 (F=64) -> d_out ----------------
__global__ void __launch_bounds__(256)
agg2_kernel(const float4* __restrict__ h, const float* __restrict__ bias,
            float4* __restrict__ out)
{
    int sub  = threadIdx.x & 15;
    int node = blockIdx.x * 16 + (threadIdx.x >> 4);

    float dv  = g_dinv[node];
    float dv2 = dv * dv;
    float4 b  = ((const float4*)bias)[sub];
    float4 sv = h[(size_t)node * 16 + sub];
    float4 acc = make_float4(b.x + sv.x * dv2, b.y + sv.y * dv2,
                             b.z + sv.z * dv2, b.w + sv.w * dv2);

    int beg = g_ptr[node], end = g_ptr[node + 1];
    for (int k = beg; k < end; k += 16) {
        int idx = k + sub;
        int2 pr = (idx < end) ? g_csr[idx] : make_int2(0, 0);
        int cnt = min(16, end - k);
        for (int i = 0; i < cnt; i++) {
            int   ss = __shfl_sync(0xffffffffu, pr.x, i, 16);
            float nn = __int_as_float(__shfl_sync(0xffffffffu, pr.y, i, 16));
            float4 v = h[(size_t)ss * 16 + sub];
            acc.x += v.x * nn; acc.y += v.y * nn;
            acc.z += v.z * nn; acc.w += v.w * nn;
        }
    }
    out[(size_t)node * 16 + sub] = acc;
}

// ---------------- launch ----------------
extern "C" void kernel_launch(void* const* d_in, const int* in_sizes, int n_in,
                              void* d_out, int out_size) {
    const float* x  = (const float*)d_in[0];
    const void*  ei = d_in[1];
    const float* W1 = (const float*)d_in[2];
    const float* b1 = (const float*)d_in[3];
    const float* W2 = (const float*)d_in[4];
    const float* b2 = (const float*)d_in[5];
    float* out = (float*)d_out;

    float *p_h1, *p_h2; u32 *p_a1h, *p_a1l, *p_w1th, *p_w1tl, *p_w2th, *p_w2tl;
    cudaGetSymbolAddress((void**)&p_h1,   g_h1);
    cudaGetSymbolAddress((void**)&p_h2,   g_h2);
    cudaGetSymbolAddress((void**)&p_a1h,  g_a1h);
    cudaGetSymbolAddress((void**)&p_a1l,  g_a1l);
    cudaGetSymbolAddress((void**)&p_w1th, g_w1th);
    cudaGetSymbolAddress((void**)&p_w1tl, g_w1tl);
    cudaGetSymbolAddress((void**)&p_w2th, g_w2th);
    cudaGetSymbolAddress((void**)&p_w2tl, g_w2tl);

    const int MGRID = (NN + 127) / 128;   // 235

    zero_deg_kernel<<<(NN + 255) / 256, 256>>>();                          // 1
    prep_edges_kernel<<<(EE + 255) / 256, 256>>>((const unsigned*)ei);     // 2
    wprep_kernel<<<(IN_C * HID_C + HID_C * OUT_C + 255) / 256, 256>>>(W1, W2); // 3
    mma_gemm<HID_C, IN_C, true><<<MGRID, 256>>>(                           // 4  <- ncu slot
        x, nullptr, nullptr, p_w1th, p_w1tl, p_h1);
    scan_dinv_kernel<<<1, 1024>>>();                                       // 5
    fill_csr_kernel<<<(EE + 255) / 256, 256>>>();                          // 6
    agg1_kernel<<<NN / 8, 256>>>((const float4*)p_h1, b1, p_a1h, p_a1l);   // 7
    mma_gemm<OUT_C, HID_C, false><<<MGRID, 256>>>(                         // 8
        nullptr, p_a1h, p_a1l, p_w2th, p_w2tl, p_h2);
    agg2_kernel<<<NN / 16, 256>>>((const float4*)p_h2, b2, (float4*)out);  // 9
}

// round 12
// speedup vs baseline: 1.0074x; 1.0074x over previous
#include <cuda_runtime.h>
#include <cuda_bf16.h>

#define NN    30000
#define EE    600000
#define IN_C  256
#define HID_C 128
#define OUT_C 64

typedef unsigned int       u32;
typedef unsigned long long u64;
typedef unsigned short     u16;

// ---------------- device scratch ----------------
__device__ int   g_src[EE];
__device__ int   g_dst[EE];
__device__ int   g_deg[NN];
__device__ float g_dinv[NN];
__device__ int   g_ptr[NN + 1];
__device__ int   g_cur[NN];
__device__ int2  g_csr[EE];
__device__ float g_h1[NN * HID_C];          // X@W1 (fp32, gathered by agg1)
__device__ u32   g_a1h[NN * HID_C / 2];     // relu(agg1) bf16-hi pairs
__device__ u32   g_a1l[NN * HID_C / 2];     // relu(agg1) bf16-lo pairs
__device__ float g_h2[NN * OUT_C];          // agg1@W2
__device__ u32   g_w1th[HID_C * IN_C / 2];  // W1^T bf16 hi  [128][256]
__device__ u32   g_w1tl[HID_C * IN_C / 2];
__device__ u32   g_w2th[OUT_C * HID_C / 2]; // W2^T bf16 hi  [64][128]
__device__ u32   g_w2tl[OUT_C * HID_C / 2];

// ---------------- helpers ----------------
__device__ __forceinline__ u32 pack_bf2(__nv_bfloat16 a, __nv_bfloat16 b) {
    return (u32)__bfloat16_as_ushort(a) | ((u32)__bfloat16_as_ushort(b) << 16);
}
__device__ __forceinline__ void split_bf(float v, __nv_bfloat16& h, __nv_bfloat16& l) {
    h = __float2bfloat16(v);
    l = __float2bfloat16(v - __bfloat162float(h));
}
__device__ __forceinline__ void ldsm4(u32* r, const void* p) {
    u32 addr = (u32)__cvta_generic_to_shared(p);
    asm volatile("ldmatrix.sync.aligned.m8n8.x4.shared.b16 {%0,%1,%2,%3}, [%4];"
                 : "=r"(r[0]), "=r"(r[1]), "=r"(r[2]), "=r"(r[3]) : "r"(addr));
}
__device__ __forceinline__ void mma_bf16(float* d, const u32* a, u32 b0, u32 b1) {
    asm volatile("mma.sync.aligned.m16n8k16.row.col.f32.bf16.bf16.f32 "
                 "{%0,%1,%2,%3}, {%4,%5,%6,%7}, {%8,%9}, {%0,%1,%2,%3};"
                 : "+f"(d[0]), "+f"(d[1]), "+f"(d[2]), "+f"(d[3])
                 : "r"(a[0]), "r"(a[1]), "r"(a[2]), "r"(a[3]), "r"(b0), "r"(b1));
}

// ---------------- prep kernels ----------------
__global__ void zero_deg_kernel() {
    int i = blockIdx.x * blockDim.x + threadIdx.x;
    if (i < NN) g_deg[i] = 0;
}

__global__ void prep_edges_kernel(const unsigned* __restrict__ raw) {
    __shared__ int s_is64;
    if (threadIdx.x == 0) {
        int is64 = 1;
        for (int i = 1; i < 64; i += 2)
            if (raw[i] != 0u) { is64 = 0; break; }
        s_is64 = is64;
    }
    __syncthreads();
    int e = blockIdx.x * blockDim.x + threadIdx.x;
    if (e >= EE) return;
    int s, d;
    if (s_is64) {
        const long long* p = (const long long*)raw;
        s = (int)p[e]; d = (int)p[EE + e];
    } else {
        const int* p = (const int*)raw;
        s = p[e]; d = p[EE + e];
    }
    g_src[e] = s;
    g_dst[e] = d;
    atomicAdd(&g_deg[d], 1);
}

// W1^T and W2^T bf16 hi/lo split (transpose to K-major rows).
__global__ void wprep_kernel(const float* __restrict__ W1, const float* __restrict__ W2) {
    int i = blockIdx.x * blockDim.x + threadIdx.x;
    u16* w1th = (u16*)g_w1th; u16* w1tl = (u16*)g_w1tl;
    u16* w2th = (u16*)g_w2th; u16* w2tl = (u16*)g_w2tl;
    if (i < IN_C * HID_C) {
        int k = i / HID_C, n = i % HID_C;
        __nv_bfloat16 h, l; split_bf(W1[i], h, l);
        w1th[n * IN_C + k] = __bfloat16_as_ushort(h);
        w1tl[n * IN_C + k] = __bfloat16_as_ushort(l);
    } else {
        int j = i - IN_C * HID_C;
        if (j < HID_C * OUT_C) {
            int k = j / OUT_C, n = j % OUT_C;
            __nv_bfloat16 h, l; split_bf(W2[j], h, l);
            w2th[n * HID_C + k] = __bfloat16_as_ushort(h);
            w2tl[n * HID_C + k] = __bfloat16_as_ushort(l);
        }
    }
}

// Fused scan + dinv: single block, 1024 threads, 30 elems/thread, warp-shfl scan.
__global__ void __launch_bounds__(1024) scan_dinv_kernel() {
    constexpr int PER = 30;   // 1024*30 = 30720 >= NN
    int tid = threadIdx.x;
    int base = tid * PER;
    int d[PER];
    int tot = 0;
#pragma unroll
    for (int i = 0; i < PER; i++) {
        int idx = base + i;
        d[i] = (idx < NN) ? g_deg[idx] : 0;
        tot += d[i];
    }
    int lane = tid & 31, warp = tid >> 5;
    int run = tot;
#pragma unroll
    for (int off = 1; off < 32; off <<= 1) {
        int n = __shfl_up_sync(0xffffffffu, run, off);
        if (lane >= off) run += n;
    }
    __shared__ int wsum[32];
    if (lane == 31) wsum[warp] = run;
    __syncthreads();
    if (warp == 0) {
        int v = wsum[lane];
        int r = v;
#pragma unroll
        for (int off = 1; off < 32; off <<= 1) {
            int n = __shfl_up_sync(0xffffffffu, r, off);
            if (lane >= off) r += n;
        }
        wsum[lane] = r - v;    // exclusive warp prefix
    }
    __syncthreads();
    int p = wsum[warp] + run - tot;  // global exclusive prefix
#pragma unroll
    for (int i = 0; i < PER; i++) {
        int idx = base + i;
        if (idx < NN) {
            g_ptr[idx] = p;
            g_cur[idx] = p;
            g_dinv[idx] = rsqrtf((float)(d[i] + 1));
        }
        p += d[i];
    }
    if (tid == 1023) g_ptr[NN] = p;
}

__global__ void fill_csr_kernel() {
    int e = blockIdx.x * blockDim.x + threadIdx.x;
    if (e >= EE) return;
    int s = g_src[e];
    int dd = g_dst[e];
    int slot = atomicAdd(&g_cur[dd], 1);
    g_csr[slot] = make_int2(s, __float_as_int(g_dinv[s] * g_dinv[dd]));
}

// ---------------- bf16x3 mma.sync GEMM:  C[M,BN] = A[M,KTOT] @ (Bt)^T ----------------
// Bt is [BN][KTOT] bf16 hi/lo (K-major = col-major B for mma row.col).
// A is fp32 (split in-kernel) or pre-split bf16 pairs.
// Block 128xBN, 8 warps in 4(m) x 2(n); warp tile 32 x (BN/2); BK=32.
template<int BN, int KTOT, bool AF32>
__global__ void __launch_bounds__(256, 1)
mma_gemm(const float* __restrict__ Af,
         const u32* __restrict__ Ah32, const u32* __restrict__ Al32,
         const u32* __restrict__ Bh, const u32* __restrict__ Bl,
         float* __restrict__ C)
{
    constexpr int BK   = 32;
    constexpr int LDS  = 40;            // padded row stride in bf16 (80B, ldmatrix conflict-free)
    constexpr int NCH  = KTOT / BK;
    constexpr int WN   = BN / 2;        // 64 (L1) or 32 (L2)
    constexpr int NI16 = WN / 16;       // 4 or 2

    __shared__ __align__(16) u16 sAh[128][LDS];
    __shared__ __align__(16) u16 sAl[128][LDS];
    __shared__ __align__(16) u16 sBh[BN][LDS];
    __shared__ __align__(16) u16 sBl[BN][LDS];

    const int tid  = threadIdx.x;
    const int warp = tid >> 5, lane = tid & 31;
    const int wm = warp & 3;            // m warp: 32*wm
    const int wn = warp >> 2;           // n warp: WN*wn
    const int m0 = blockIdx.x * 128;
    const int sub = lane >> 3, r8 = lane & 7;

    float acc[2][2 * NI16][4];
#pragma unroll
    for (int i = 0; i < 2; i++)
#pragma unroll
        for (int j = 0; j < 2 * NI16; j++)
#pragma unroll
            for (int q = 0; q < 4; q++) acc[i][j][q] = 0.0f;

    for (int c = 0; c < NCH; c++) {
        // ---- load A chunk (128 x 32) ----
        if (AF32) {
            for (int idx = tid; idx < 1024; idx += 256) {     // 128 rows x 8 float4
                int row = idx >> 3, f4 = idx & 7;
                int gm = m0 + row;
                float4 v = make_float4(0.f, 0.f, 0.f, 0.f);
                if (gm < NN) v = *(const float4*)(Af + (size_t)gm * KTOT + c * BK + f4 * 4);
                __nv_bfloat16 hx, lx, hy, ly, hz, lz, hw, lw;
                split_bf(v.x, hx, lx); split_bf(v.y, hy, ly);
                split_bf(v.z, hz, lz); split_bf(v.w, hw, lw);
                *(uint2*)&sAh[row][f4 * 4] = make_uint2(pack_bf2(hx, hy), pack_bf2(hz, hw));
                *(uint2*)&sAl[row][f4 * 4] = make_uint2(pack_bf2(lx, ly), pack_bf2(lz, lw));
            }
        } else {
            for (int idx = tid; idx < 2048; idx += 256) {     // 128 rows x 16 u32
                int row = idx >> 4, uu = idx & 15;
                int gm = m0 + row;
                u32 hv = 0, lv = 0;
                if (gm < NN) {
                    size_t g = (size_t)gm * (KTOT / 2) + c * (BK / 2) + uu;
                    hv = Ah32[g]; lv = Al32[g];
                }
                *(u32*)&sAh[row][uu * 2] = hv;
                *(u32*)&sAl[row][uu * 2] = lv;
            }
        }
        // ---- load B chunk (BN x 32) ----
        for (int idx = tid; idx < BN * 16; idx += 256) {
            int row = idx >> 4, uu = idx & 15;
            size_t g = (size_t)row * (KTOT / 2) + c * (BK / 2) + uu;
            *(u32*)&sBh[row][uu * 2] = Bh[g];
            *(u32*)&sBl[row][uu * 2] = Bl[g];
        }
        __syncthreads();

#pragma unroll
        for (int kk = 0; kk < BK; kk += 16) {
            // A fragments (hi+lo) for this warp's 32 rows
            u32 ah[2][4], al[2][4];
#pragma unroll
            for (int mi = 0; mi < 2; mi++) {
                int arow = wm * 32 + mi * 16 + ((sub & 1) << 3) + r8;
                int acol = kk + ((sub >> 1) << 3);
                ldsm4(ah[mi], &sAh[arow][acol]);
                ldsm4(al[mi], &sAl[arow][acol]);
            }
#pragma unroll
            for (int ni = 0; ni < NI16; ni++) {
                int brow = wn * WN + ni * 16 + ((sub >> 1) << 3) + r8;
                int bcol = kk + ((sub & 1) << 3);
                u32 bh[4], bl[4];
                ldsm4(bh, &sBh[brow][bcol]);
                ldsm4(bl, &sBl[brow][bcol]);
#pragma unroll
                for (int mi = 0; mi < 2; mi++) {
                    mma_bf16(acc[mi][ni * 2 + 0], ah[mi], bh[0], bh[1]);
                    mma_bf16(acc[mi][ni * 2 + 1], ah[mi], bh[2], bh[3]);
                    mma_bf16(acc[mi][ni * 2 + 0], ah[mi], bl[0], bl[1]);
                    mma_bf16(acc[mi][ni * 2 + 1], ah[mi], bl[2], bl[3]);
                    mma_bf16(acc[mi][ni * 2 + 0], al[mi], bh[0], bh[1]);
                    mma_bf16(acc[mi][ni * 2 + 1], al[mi], bh[2], bh[3]);
                }
            }
        }
        __syncthreads();
    }

    // ---- epilogue ----
#pragma unroll
    for (int mi = 0; mi < 2; mi++) {
#pragma unroll
        for (int j = 0; j < 2 * NI16; j++) {
            int row = m0 + wm * 32 + mi * 16 + (lane >> 2);
            int col = wn * WN + j * 8 + (lane & 3) * 2;
            float* dst = C + (size_t)row * BN + col;
            if (row < NN) {
                dst[0] = acc[mi][j][0];
                dst[1] = acc[mi][j][1];
            }
            if (row + 8 < NN) {
                dst[8 * BN + 0] = acc[mi][j][2];
                dst[8 * BN + 1] = acc[mi][j][3];
            }
        }
    }
}

// ---------------- CSR pull-aggregation, layer 1 (F=128) ----------------
// out = relu(b1 + h[n]*dinv^2 + sum h[src]*norm), written as bf16 hi/lo pairs.
__global__ void __launch_bounds__(256)
agg1_kernel(const float4* __restrict__ h, const float* __restrict__ bias,
            u32* __restrict__ outh, u32* __restrict__ outl)
{
    int warp = threadIdx.x >> 5;
    int lane = threadIdx.x & 31;
    int node = blockIdx.x * 8 + warp;

    float dv  = g_dinv[node];
    float dv2 = dv * dv;
    float4 b  = ((const float4*)bias)[lane];
    float4 sv = h[(size_t)node * 32 + lane];
    float4 acc = make_float4(b.x + sv.x * dv2, b.y + sv.y * dv2,
                             b.z + sv.z * dv2, b.w + sv.w * dv2);

    int beg = g_ptr[node], end = g_ptr[node + 1];
    for (int k = beg; k < end; k += 32) {
        int idx = k + lane;
        int2 pr = (idx < end) ? g_csr[idx] : make_int2(0, 0);
        int cnt = min(32, end - k);
        for (int i = 0; i < cnt; i++) {
            int   ss = __shfl_sync(0xffffffffu, pr.x, i);
            float nn = __int_as_float(__shfl_sync(0xffffffffu, pr.y, i));
            float4 v = h[(size_t)ss * 32 + lane];
            acc.x += v.x * nn; acc.y += v.y * nn;
            acc.z += v.z * nn; acc.w += v.w * nn;
        }
    }
    float4 v = make_float4(fmaxf(acc.x, 0.f), fmaxf(acc.y, 0.f),
                           fmaxf(acc.z, 0.f), fmaxf(acc.w, 0.f));
    __nv_bfloat16 hx, lx, hy, ly, hz, lz, hw, lw;
    split_bf(v.x, hx, lx); split_bf(v.y, hy, ly);
    split_bf(v.z, hz, lz); split_bf(v.w, hw, lw);
    size_t o = (size_t)node * 64 + lane * 2;
    *(uint2*)(outh + o) = make_uint2(pack_bf2(hx, hy), pack_bf2(hz, hw));
    *(uint2*)(outl + o) = make_uint2(pack_bf2(lx, ly), pack_bf2(lz, lw));
}

// ---------------- CSR pull-aggregation, layer 2 (F=64) -> d_out ----------------
__global__ void __launch_bounds__(256)
agg2_kernel(const float4* __restrict__ h, const float* __restrict__ bias,
            float4* __restrict__ out)
{
    int sub  = threadIdx.x & 15;
    int node = blockIdx.x * 16 + (threadIdx.x >> 4);

    float dv  = g_dinv[node];
    float dv2 = dv * dv;
    float4 b  = ((const float4*)bias)[sub];
    float4 sv = h[(size_t)node * 16 + sub];
    float4 acc = make_float4(b.x + sv.x * dv2, b.y + sv.y * dv2,
                             b.z + sv.z * dv2, b.w + sv.w * dv2);

    int beg = g_ptr[node], end = g_ptr[node + 1];
    for (int k = beg; k < end; k += 16) {
        int idx = k + sub;
        int2 pr = (idx < end) ? g_csr[idx] : make_int2(0, 0);
        int cnt = min(16, end - k);
        for (int i = 0; i < cnt; i++) {
            int   ss = __shfl_sync(0xffffffffu, pr.x, i, 16);
            float nn = __int_as_float(__shfl_sync(0xffffffffu, pr.y, i, 16));
            float4 v = h[(size_t)ss * 16 + sub];
            acc.x += v.x * nn; acc.y += v.y * nn;
            acc.z += v.z * nn; acc.w += v.w * nn;
        }
    }
    out[(size_t)node * 16 + sub] = acc;
}

// ---------------- launch ----------------
extern "C" void kernel_launch(void* const* d_in, const int* in_sizes, int n_in,
                              void* d_out, int out_size) {
    const float* x  = (const float*)d_in[0];
    const void*  ei = d_in[1];
    const float* W1 = (const float*)d_in[2];
    const float* b1 = (const float*)d_in[3];
    const float* W2 = (const float*)d_in[4];
    const float* b2 = (const float*)d_in[5];
    float* out = (float*)d_out;

    float *p_h1, *p_h2; u32 *p_a1h, *p_a1l, *p_w1th, *p_w1tl, *p_w2th, *p_w2tl;
    cudaGetSymbolAddress((void**)&p_h1,   g_h1);
    cudaGetSymbolAddress((void**)&p_h2,   g_h2);
    cudaGetSymbolAddress((void**)&p_a1h,  g_a1h);
    cudaGetSymbolAddress((void**)&p_a1l,  g_a1l);
    cudaGetSymbolAddress((void**)&p_w1th, g_w1th);
    cudaGetSymbolAddress((void**)&p_w1tl, g_w1tl);
    cudaGetSymbolAddress((void**)&p_w2th, g_w2th);
    cudaGetSymbolAddress((void**)&p_w2tl, g_w2tl);

    const int MGRID = (NN + 127) / 128;   // 235

    zero_deg_kernel<<<(NN + 255) / 256, 256>>>();                          // 1
    prep_edges_kernel<<<(EE + 255) / 256, 256>>>((const unsigned*)ei);     // 2
    wprep_kernel<<<(IN_C * HID_C + HID_C * OUT_C + 255) / 256, 256>>>(W1, W2); // 3
    mma_gemm<HID_C, IN_C, true><<<MGRID, 256>>>(                           // 4  <- ncu slot
        x, nullptr, nullptr, p_w1th, p_w1tl, p_h1);
    scan_dinv_kernel<<<1, 1024>>>();                                       // 5
    fill_csr_kernel<<<(EE + 255) / 256, 256>>>();                          // 6
    agg1_kernel<<<NN / 8, 256>>>((const float4*)p_h1, b1, p_a1h, p_a1l);   // 7
    mma_gemm<OUT_C, HID_C, false><<<MGRID, 256>>>(                         // 8
        nullptr, p_a1h, p_a1l, p_w2th, p_w2tl, p_h2);
    agg2_kernel<<<NN / 16, 256>>>((const float4*)p_h2, b2, (float4*)out);  // 9
}

// round 13
// speedup vs baseline: 1.0127x; 1.0052x over previous
#include <cuda_runtime.h>
#include <cuda_bf16.h>

#define NN    30000
#define EE    600000
#define IN_C  256
#define HID_C 128
#define OUT_C 64

typedef unsigned int       u32;
typedef unsigned long long u64;
typedef unsigned short     u16;

// ---------------- device scratch ----------------
__device__ int   g_src[EE];
__device__ int   g_dst[EE];
__device__ int   g_deg[NN];
__device__ float g_dinv[NN];
__device__ int   g_ptr[NN + 1];
__device__ int   g_cur[NN];
__device__ int2  g_csr[EE];
__device__ float g_h1[NN * HID_C];          // X@W1 (fp32, gathered by agg1)
__device__ u32   g_a1h[NN * HID_C / 2];     // relu(agg1) bf16-hi pairs
__device__ u32   g_a1l[NN * HID_C / 2];     // relu(agg1) bf16-lo pairs
__device__ float g_h2[NN * OUT_C];          // agg1@W2
__device__ u32   g_w1th[HID_C * IN_C / 2];  // W1^T bf16 hi  [128][256]
__device__ u32   g_w1tl[HID_C * IN_C / 2];
__device__ u32   g_w2th[OUT_C * HID_C / 2]; // W2^T bf16 hi  [64][128]
__device__ u32   g_w2tl[OUT_C * HID_C / 2];

// ---------------- helpers ----------------
__device__ __forceinline__ u32 pack_bf2(__nv_bfloat16 a, __nv_bfloat16 b) {
    return (u32)__bfloat16_as_ushort(a) | ((u32)__bfloat16_as_ushort(b) << 16);
}
__device__ __forceinline__ void split_bf(float v, __nv_bfloat16& h, __nv_bfloat16& l) {
    h = __float2bfloat16(v);
    l = __float2bfloat16(v - __bfloat162float(h));
}
__device__ __forceinline__ void ldsm4(u32* r, const void* p) {
    u32 addr = (u32)__cvta_generic_to_shared(p);
    asm volatile("ldmatrix.sync.aligned.m8n8.x4.shared.b16 {%0,%1,%2,%3}, [%4];"
                 : "=r"(r[0]), "=r"(r[1]), "=r"(r[2]), "=r"(r[3]) : "r"(addr));
}
__device__ __forceinline__ void mma_bf16(float* d, const u32* a, u32 b0, u32 b1) {
    asm volatile("mma.sync.aligned.m16n8k16.row.col.f32.bf16.bf16.f32 "
                 "{%0,%1,%2,%3}, {%4,%5,%6,%7}, {%8,%9}, {%0,%1,%2,%3};"
                 : "+f"(d[0]), "+f"(d[1]), "+f"(d[2]), "+f"(d[3])
                 : "r"(a[0]), "r"(a[1]), "r"(a[2]), "r"(a[3]), "r"(b0), "r"(b1));
}

// ---------------- prep kernels ----------------
__global__ void zero_deg_kernel() {
    int i = blockIdx.x * blockDim.x + threadIdx.x;
    if (i < NN) g_deg[i] = 0;
}

__global__ void prep_edges_kernel(const unsigned* __restrict__ raw) {
    __shared__ int s_is64;
    if (threadIdx.x == 0) {
        int is64 = 1;
        for (int i = 1; i < 64; i += 2)
            if (raw[i] != 0u) { is64 = 0; break; }
        s_is64 = is64;
    }
    __syncthreads();
    int e = blockIdx.x * blockDim.x + threadIdx.x;
    if (e >= EE) return;
    int s, d;
    if (s_is64) {
        const long long* p = (const long long*)raw;
        s = (int)p[e]; d = (int)p[EE + e];
    } else {
        const int* p = (const int*)raw;
        s = p[e]; d = p[EE + e];
    }
    g_src[e] = s;
    g_dst[e] = d;
    atomicAdd(&g_deg[d], 1);
}

// W1^T and W2^T bf16 hi/lo split (transpose to K-major rows).
__global__ void wprep_kernel(const float* __restrict__ W1, const float* __restrict__ W2) {
    int i = blockIdx.x * blockDim.x + threadIdx.x;
    u16* w1th = (u16*)g_w1th; u16* w1tl = (u16*)g_w1tl;
    u16* w2th = (u16*)g_w2th; u16* w2tl = (u16*)g_w2tl;
    if (i < IN_C * HID_C) {
        int k = i / HID_C, n = i % HID_C;
        __nv_bfloat16 h, l; split_bf(W1[i], h, l);
        w1th[n * IN_C + k] = __bfloat16_as_ushort(h);
        w1tl[n * IN_C + k] = __bfloat16_as_ushort(l);
    } else {
        int j = i - IN_C * HID_C;
        if (j < HID_C * OUT_C) {
            int k = j / OUT_C, n = j % OUT_C;
            __nv_bfloat16 h, l; split_bf(W2[j], h, l);
            w2th[n * HID_C + k] = __bfloat16_as_ushort(h);
            w2tl[n * HID_C + k] = __bfloat16_as_ushort(l);
        }
    }
}

// Fused scan + dinv: single block, 1024 threads, 30 elems/thread, warp-shfl scan.
__global__ void __launch_bounds__(1024) scan_dinv_kernel() {
    constexpr int PER = 30;   // 1024*30 = 30720 >= NN
    int tid = threadIdx.x;
    int base = tid * PER;
    int d[PER];
    int tot = 0;
#pragma unroll
    for (int i = 0; i < PER; i++) {
        int idx = base + i;
        d[i] = (idx < NN) ? g_deg[idx] : 0;
        tot += d[i];
    }
    int lane = tid & 31, warp = tid >> 5;
    int run = tot;
#pragma unroll
    for (int off = 1; off < 32; off <<= 1) {
        int n = __shfl_up_sync(0xffffffffu, run, off);
        if (lane >= off) run += n;
    }
    __shared__ int wsum[32];
    if (lane == 31) wsum[warp] = run;
    __syncthreads();
    if (warp == 0) {
        int v = wsum[lane];
        int r = v;
#pragma unroll
        for (int off = 1; off < 32; off <<= 1) {
            int n = __shfl_up_sync(0xffffffffu, r, off);
            if (lane >= off) r += n;
        }
        wsum[lane] = r - v;    // exclusive warp prefix
    }
    __syncthreads();
    int p = wsum[warp] + run - tot;  // global exclusive prefix
#pragma unroll
    for (int i = 0; i < PER; i++) {
        int idx = base + i;
        if (idx < NN) {
            g_ptr[idx] = p;
            g_cur[idx] = p;
            g_dinv[idx] = rsqrtf((float)(d[i] + 1));
        }
        p += d[i];
    }
    if (tid == 1023) g_ptr[NN] = p;
}

__global__ void fill_csr_kernel() {
    int e = blockIdx.x * blockDim.x + threadIdx.x;
    if (e >= EE) return;
    int s = g_src[e];
    int dd = g_dst[e];
    int slot = atomicAdd(&g_cur[dd], 1);
    g_csr[slot] = make_int2(s, __float_as_int(g_dinv[s] * g_dinv[dd]));
}

// ---------------- bf16x3 mma.sync GEMM:  C[M,BN] = A[M,KTOT] @ (Bt)^T ----------------
// Bt is [BN][KTOT] bf16 hi/lo (K-major = col-major B for mma row.col).
// A is fp32 (split in-kernel) or pre-split bf16 pairs.
// Block 128xBN, 8 warps in 4(m) x 2(n); warp tile 32 x (BN/2); BK=32.
template<int BN, int KTOT, bool AF32>
__global__ void __launch_bounds__(256, 1)
mma_gemm(const float* __restrict__ Af,
         const u32* __restrict__ Ah32, const u32* __restrict__ Al32,
         const u32* __restrict__ Bh, const u32* __restrict__ Bl,
         float* __restrict__ C)
{
    constexpr int BK   = 32;
    constexpr int LDS  = 40;            // padded row stride in bf16 (80B, ldmatrix conflict-free)
    constexpr int NCH  = KTOT / BK;
    constexpr int WN   = BN / 2;        // 64 (L1) or 32 (L2)
    constexpr int NI16 = WN / 16;       // 4 or 2

    __shared__ __align__(16) u16 sAh[128][LDS];
    __shared__ __align__(16) u16 sAl[128][LDS];
    __shared__ __align__(16) u16 sBh[BN][LDS];
    __shared__ __align__(16) u16 sBl[BN][LDS];

    const int tid  = threadIdx.x;
    const int warp = tid >> 5, lane = tid & 31;
    const int wm = warp & 3;            // m warp: 32*wm
    const int wn = warp >> 2;           // n warp: WN*wn
    const int m0 = blockIdx.x * 128;
    const int sub = lane >> 3, r8 = lane & 7;

    float acc[2][2 * NI16][4];
#pragma unroll
    for (int i = 0; i < 2; i++)
#pragma unroll
        for (int j = 0; j < 2 * NI16; j++)
#pragma unroll
            for (int q = 0; q < 4; q++) acc[i][j][q] = 0.0f;

    for (int c = 0; c < NCH; c++) {
        // ---- load A chunk (128 x 32) ----
        if (AF32) {
            for (int idx = tid; idx < 1024; idx += 256) {     // 128 rows x 8 float4
                int row = idx >> 3, f4 = idx & 7;
                int gm = m0 + row;
                float4 v = make_float4(0.f, 0.f, 0.f, 0.f);
                if (gm < NN) v = *(const float4*)(Af + (size_t)gm * KTOT + c * BK + f4 * 4);
                __nv_bfloat16 hx, lx, hy, ly, hz, lz, hw, lw;
                split_bf(v.x, hx, lx); split_bf(v.y, hy, ly);
                split_bf(v.z, hz, lz); split_bf(v.w, hw, lw);
                *(uint2*)&sAh[row][f4 * 4] = make_uint2(pack_bf2(hx, hy), pack_bf2(hz, hw));
                *(uint2*)&sAl[row][f4 * 4] = make_uint2(pack_bf2(lx, ly), pack_bf2(lz, lw));
            }
        } else {
            for (int idx = tid; idx < 2048; idx += 256) {     // 128 rows x 16 u32
                int row = idx >> 4, uu = idx & 15;
                int gm = m0 + row;
                u32 hv = 0, lv = 0;
                if (gm < NN) {
                    size_t g = (size_t)gm * (KTOT / 2) + c * (BK / 2) + uu;
                    hv = Ah32[g]; lv = Al32[g];
                }
                *(u32*)&sAh[row][uu * 2] = hv;
                *(u32*)&sAl[row][uu * 2] = lv;
            }
        }
        // ---- load B chunk (BN x 32) ----
        for (int idx = tid; idx < BN * 16; idx += 256) {
            int row = idx >> 4, uu = idx & 15;
            size_t g = (size_t)row * (KTOT / 2) + c * (BK / 2) + uu;
            *(u32*)&sBh[row][uu * 2] = Bh[g];
            *(u32*)&sBl[row][uu * 2] = Bl[g];
        }
        __syncthreads();

#pragma unroll
        for (int kk = 0; kk < BK; kk += 16) {
            // A fragments (hi+lo) for this warp's 32 rows
            u32 ah[2][4], al[2][4];
#pragma unroll
            for (int mi = 0; mi < 2; mi++) {
                int arow = wm * 32 + mi * 16 + ((sub & 1) << 3) + r8;
                int acol = kk + ((sub >> 1) << 3);
                ldsm4(ah[mi], &sAh[arow][acol]);
                ldsm4(al[mi], &sAl[arow][acol]);
            }
#pragma unroll
            for (int ni = 0; ni < NI16; ni++) {
                int brow = wn * WN + ni * 16 + ((sub >> 1) << 3) + r8;
                int bcol = kk + ((sub & 1) << 3);
                u32 bh[4], bl[4];
                ldsm4(bh, &sBh[brow][bcol]);
                ldsm4(bl, &sBl[brow][bcol]);
#pragma unroll
                for (int mi = 0; mi < 2; mi++) {
                    mma_bf16(acc[mi][ni * 2 + 0], ah[mi], bh[0], bh[1]);
                    mma_bf16(acc[mi][ni * 2 + 1], ah[mi], bh[2], bh[3]);
                    mma_bf16(acc[mi][ni * 2 + 0], ah[mi], bl[0], bl[1]);
                    mma_bf16(acc[mi][ni * 2 + 1], ah[mi], bl[2], bl[3]);
                    mma_bf16(acc[mi][ni * 2 + 0], al[mi], bh[0], bh[1]);
                    mma_bf16(acc[mi][ni * 2 + 1], al[mi], bh[2], bh[3]);
                }
            }
        }
        __syncthreads();
    }

    // ---- epilogue ----
#pragma unroll
    for (int mi = 0; mi < 2; mi++) {
#pragma unroll
        for (int j = 0; j < 2 * NI16; j++) {
            int row = m0 + wm * 32 + mi * 16 + (lane >> 2);
            int col = wn * WN + j * 8 + (lane & 3) * 2;
            float* dst = C + (size_t)row * BN + col;
            if (row < NN) {
                dst[0] = acc[mi][j][0];
                dst[1] = acc[mi][j][1];
            }
            if (row + 8 < NN) {
                dst[8 * BN + 0] = acc[mi][j][2];
                dst[8 * BN + 1] = acc[mi][j][3];
            }
        }
    }
}

// ---------------- CSR pull-aggregation, layer 1 (F=128) ----------------
// out = relu(b1 + h[n]*dinv^2 + sum h[src]*norm), written as bf16 hi/lo pairs.
__global__ void __launch_bounds__(256)
agg1_kernel(const float4* __restrict__ h, const float* __restrict__ bias,
            u32* __restrict__ outh, u32* __restrict__ outl)
{
    int warp = threadIdx.x >> 5;
    int lane = threadIdx.x & 31;
    int node = blockIdx.x * 8 + warp;

    float dv  = g_dinv[node];
    float dv2 = dv * dv;
    float4 b  = ((const float4*)bias)[lane];
    float4 sv = h[(size_t)node * 32 + lane];
    float4 acc = make_float4(b.x + sv.x * dv2, b.y + sv.y * dv2,
                             b.z + sv.z * dv2, b.w + sv.w * dv2);

    int beg = g_ptr[node], end = g_ptr[node + 1];
    for (int k = beg; k < end; k += 32) {
        int idx = k + lane;
        int2 pr = (idx < end) ? g_csr[idx] : make_int2(0, 0);
        int cnt = min(32, end - k);
        for (int i = 0; i < cnt; i++) {
            int   ss = __shfl_sync(0xffffffffu, pr.x, i);
            float nn = __int_as_float(__shfl_sync(0xffffffffu, pr.y, i));
            float4 v = h[(size_t)ss * 32 + lane];
            acc.x += v.x * nn; acc.y += v.y * nn;
            acc.z += v.z * nn; acc.w += v.w * nn;
        }
    }
    float4 v = make_float4(fmaxf(acc.x, 0.f), fmaxf(acc.y, 0.f),
                           fmaxf(acc.z, 0.f), fmaxf(acc.w, 0.f));
    __nv_bfloat16 hx, lx, hy, ly, hz, lz, hw, lw;
    split_bf(v.x, hx, lx); split_bf(v.y, hy, ly);
    split_bf(v.z, hz, lz); split_bf(v.w, hw, lw);
    size_t o = (size_t)node * 64 + lane * 2;
    *(uint2*)(outh + o) = make_uint2(pack_bf2(hx, hy), pack_bf2(hz, hw));
    *(uint2*)(outl + o) = make_uint2(pack_bf2(lx, ly), pack_bf2(lz, lw));
}

// ---------------- CSR pull-aggregation, layer 2 (F=64) -> d_out ----------------
__global__ void __launch_bounds__(256)
agg2_kernel(const float4* __restrict__ h, const float* __restrict__ bias,
            float4* __restrict__ out)
{
    int sub  = threadIdx.x & 15;
    int node = blockIdx.x * 16 + (threadIdx.x >> 4);

    float dv  = g_dinv[node];
    float dv2 = dv * dv;
    float4 b  = ((const float4*)bias)[sub];
    float4 sv = h[(size_t)node * 16 + sub];
    float4 acc = make_float4(b.x + sv.x * dv2, b.y + sv.y * dv2,
                             b.z + sv.z * dv2, b.w + sv.w * dv2);

    int beg = g_ptr[node], end = g_ptr[node + 1];
    for (int k = beg; k < end; k += 16) {
        int idx = k + sub;
        int2 pr = (idx < end) ? g_csr[idx] : make_int2(0, 0);
        int cnt = min(16, end - k);
        for (int i = 0; i < cnt; i++) {
            int   ss = __shfl_sync(0xffffffffu, pr.x, i, 16);
            float nn = __int_as_float(__shfl_sync(0xffffffffu, pr.y, i, 16));
            float4 v = h[(size_t)ss * 16 + sub];
            acc.x += v.x * nn; acc.y += v.y * nn;
            acc.z += v.z * nn; acc.w += v.w * nn;
        }
    }
    out[(size_t)node * 16 + sub] = acc;
}

// ---------------- launch ----------------
extern "C" void kernel_launch(void* const* d_in, const int* in_sizes, int n_in,
                              void* d_out, int out_size) {
    const float* x  = (const float*)d_in[0];
    const void*  ei = d_in[1];
    const float* W1 = (const float*)d_in[2];
    const float* b1 = (const float*)d_in[3];
    const float* W2 = (const float*)d_in[4];
    const float* b2 = (const float*)d_in[5];
    float* out = (float*)d_out;

    float *p_h1, *p_h2; u32 *p_a1h, *p_a1l, *p_w1th, *p_w1tl, *p_w2th, *p_w2tl;
    cudaGetSymbolAddress((void**)&p_h1,   g_h1);
    cudaGetSymbolAddress((void**)&p_h2,   g_h2);
    cudaGetSymbolAddress((void**)&p_a1h,  g_a1h);
    cudaGetSymbolAddress((void**)&p_a1l,  g_a1l);
    cudaGetSymbolAddress((void**)&p_w1th, g_w1th);
    cudaGetSymbolAddress((void**)&p_w1tl, g_w1tl);
    cudaGetSymbolAddress((void**)&p_w2th, g_w2th);
    cudaGetSymbolAddress((void**)&p_w2tl, g_w2tl);

    const int MGRID = (NN + 127) / 128;   // 235

    zero_deg_kernel<<<(NN + 255) / 256, 256>>>();                          // 1
    prep_edges_kernel<<<(EE + 255) / 256, 256>>>((const unsigned*)ei);     // 2
    wprep_kernel<<<(IN_C * HID_C + HID_C * OUT_C + 255) / 256, 256>>>(W1, W2); // 3
    mma_gemm<HID_C, IN_C, true><<<MGRID, 256>>>(                           // 4  <- ncu slot
        x, nullptr, nullptr, p_w1th, p_w1tl, p_h1);
    scan_dinv_kernel<<<1, 1024>>>();                                       // 5
    fill_csr_kernel<<<(EE + 255) / 256, 256>>>();                          // 6
    agg1_kernel<<<NN / 8, 256>>>((const float4*)p_h1, b1, p_a1h, p_a1l);   // 7
    mma_gemm<OUT_C, HID_C, false><<<MGRID, 256>>>(                         // 8
        nullptr, p_a1h, p_a1l, p_w2th, p_w2tl, p_h2);
    agg2_kernel<<<NN / 16, 256>>>((const float4*)p_h2, b2, (float4*)out);  // 9
}